// round 15
// baseline (speedup 1.0000x reference)
#include <cuda_runtime.h>

// Fused upsample2x-bilinear -> affine_grid -> grid_sample_bilinear.
// Separable composition: output = 3x3 weighted sum over ORIGINAL image.
// R15: (a) fully predicated taps: zero-weight taps skip BOTH the load and
// the FMAs (no zero-init movs needed); (b) vectorized transpose prepass
// (LDG.128 in, STG.128 out, conflict-free SMEM column gathers).

#define N_   8
#define C_   32
#define HI   256
#define WI   256
#define HU   512
#define WU   512

// NHWC scratch: 8*256*256*32 floats = 67 MB (device global: allocation-free)
__device__ float4 g_nhwc4[N_ * HI * WI * (C_ / 4)];

// ---------------- prepass: NCHW -> NHWC, one (n,h) row per block ----------------
__global__ void __launch_bounds__(256)
transpose_nhwc(const float* __restrict__ x) {
    __shared__ float sm[C_][WI + 1];     // stride 257 = 1 mod 32
    int t  = threadIdx.x;
    int bh = blockIdx.x;                  // n*HI + h
    int n = bh >> 8, h = bh & 255;

    const float* ip = x + (((long long)n * C_) * HI + h) * WI;

    // Load: 32 channel-rows x 256 floats, LDG.128 coalesced (1KB per c-row)
    int cb = t >> 6;                      // 0..3
    int wi = (t & 63) << 2;               // float index (16B granular)
    #pragma unroll
    for (int k = 0; k < 8; k++) {
        int c = (k << 2) | cb;
        float4 v = *(const float4*)(ip + (long long)c * (HI * WI) + wi);
        sm[c][wi + 0] = v.x;              // row stride 1028B: scalar STS
        sm[c][wi + 1] = v.y;
        sm[c][wi + 2] = v.z;
        sm[c][wi + 3] = v.w;
    }
    __syncthreads();

    // Store: NHWC, STG.128 coalesced. Warp covers 4 points x 32 ch per pass.
    float* op = (float*)g_nhwc4 + ((long long)n * HI + h) * (WI * C_);
    int wrp  = t >> 5;
    int lane = t & 31;
    int q  = lane & 7;                    // channel quad
    int pl = lane >> 3;                   // point within warp group
    #pragma unroll
    for (int pass = 0; pass < 8; pass++) {
        int p = (pass << 5) | (wrp << 2) | pl;
        float4 v;                         // bank = (4q + i + p) % 32: distinct
        v.x = sm[(q << 2) + 0][p];
        v.y = sm[(q << 2) + 1][p];
        v.z = sm[(q << 2) + 2][p];
        v.w = sm[(q << 2) + 3][p];
        *(float4*)(op + p * C_ + (q << 2)) = v;
    }
}

// ---------------- main fused kernel ----------------
__device__ __forceinline__ void axis_taps(float f, int U, int O,
                                          int& base, float w[3]) {
    float f0 = floorf(f);
    int   i0 = (int)f0;
    float wf = f - f0;

    w[0] = 0.f; w[1] = 0.f; w[2] = 0.f;
    base = 0;

    #pragma unroll
    for (int k = 0; k < 2; k++) {
        int   t  = i0 + k;
        float Wk = (k == 0) ? (1.0f - wf) : wf;
        Wk = (t >= 0 && t < U) ? Wk : 0.0f;          // zero-padding validity
        int tc = min(max(t, 0), U - 1);
        float s  = fmaxf((float)tc * 0.5f - 0.25f, 0.0f);  // upsample source
        int   o0 = (int)s;
        float wu = s - (float)o0;
        int   o1 = min(o0 + 1, O - 1);
        if (k == 0) base = o0;                       // taps are monotone
        w[o0 - base] += Wk * (1.0f - wu);
        w[o1 - base] += Wk * wu;
    }
}

// Predicated 128-bit load, NO zero-init: when w == 0 the destination holds
// garbage, but the matching FMA is predicated off by the same condition.
__device__ __forceinline__ void pred_load2(unsigned long long& a,
                                           unsigned long long& b,
                                           const float4* addr, float w) {
    asm("{\n\t"
        ".reg .pred p;\n\t"
        "setp.ne.f32 p, %2, 0f00000000;\n\t"
        "@p ld.global.nc.v2.b64 {%0, %1}, [%3];\n\t"
        "}"
        : "=l"(a), "=l"(b)
        : "f"(w), "l"((const void*)addr));
}

// Predicated pair of packed FMAs guarded by w != 0 (recomputed setp keeps
// this asm block independent of the load block, preserving MLP).
__device__ __forceinline__ void pred_fma2(unsigned long long& acc01,
                                          unsigned long long& acc23,
                                          unsigned long long t0,
                                          unsigned long long t1,
                                          unsigned long long w2, float w) {
    asm("{\n\t"
        ".reg .pred p;\n\t"
        "setp.ne.f32 p, %2, 0f00000000;\n\t"
        "@p fma.rn.f32x2 %0, %3, %5, %0;\n\t"
        "@p fma.rn.f32x2 %1, %4, %5, %1;\n\t"
        "}"
        : "+l"(acc01), "+l"(acc23)
        : "f"(w), "l"(t0), "l"(t1), "l"(w2));
}

#define PACK2(d, s)   asm("mov.b64 %0, {%1, %1};" : "=l"(d) : "f"(s))
#define UNPACK2(lo, hi, s) \
    asm("mov.b64 {%0, %1}, %2;" : "=f"(lo), "=f"(hi) : "l"(s))

__global__ void __launch_bounds__(256, 4)
fused_gather_nhwc(const float* __restrict__ theta,
                  float* __restrict__ out) {
    __shared__ float obuf[8][C_][33];           // [warp][channel][point]
    // per-point tap table: [0..8]=wij row-major, [12..15]=ro4, [16..19]=co4
    __shared__ __align__(16) float tap[8][32][20];

    const unsigned FULL = 0xFFFFFFFFu;
    int w    = threadIdx.x >> 5;
    int lane = threadIdx.x & 31;
    int wid  = blockIdx.x * 8 + w;
    int n   = wid >> 13;                 // 8192 warps per image
    int r   = wid & 8191;
    int yo  = r >> 4;                    // 512 rows
    int xo0 = (r & 15) << 5;             // 16 x-segments of 32

    float* outp = out + ((long long)n * C_) * (HU * WU)
                      + (long long)yo * WU + xo0;

    const float* th = theta + n * 6;
    float t0 = __ldg(th + 0), t1 = __ldg(th + 1), t2 = __ldg(th + 2);
    float t3 = __ldg(th + 3), t4 = __ldg(th + 4), t5 = __ldg(th + 5);
    float gyn = (2.0f * (float)yo + 1.0f) / (float)HU - 1.0f;

    // ---- per-lane taps for point (xo0+lane, yo) -> SMEM table ----
    int z;
    {
        int xo = xo0 + lane;
        float gxn = (2.0f * (float)xo + 1.0f) / (float)WU - 1.0f;
        float gox = t0 * gxn + t1 * gyn + t2;
        float goy = t3 * gxn + t4 * gyn + t5;
        float ix = ((gox + 1.0f) * (float)WU - 1.0f) * 0.5f;
        float iy = ((goy + 1.0f) * (float)HU - 1.0f) * 0.5f;

        int by, bx;
        float wy[3], wx[3];
        axis_taps(iy, HU, HI, by, wy);
        axis_taps(ix, WU, WI, bx, wx);

        float* tp = tap[w][lane];
        *(float4*)(tp + 0) = make_float4(wy[0]*wx[0], wy[0]*wx[1],
                                         wy[0]*wx[2], wy[1]*wx[0]);
        *(float4*)(tp + 4) = make_float4(wy[1]*wx[1], wy[1]*wx[2],
                                         wy[2]*wx[0], wy[2]*wx[1]);
        tp[8] = wy[2]*wx[2];
        *(int4*)(tp + 12) = make_int4(min(by,     HI - 1) * (WI * (C_ / 4)),
                                      min(by + 1, HI - 1) * (WI * (C_ / 4)),
                                      min(by + 2, HI - 1) * (WI * (C_ / 4)), 0);
        *(int4*)(tp + 16) = make_int4(min(bx,     WI - 1) * (C_ / 4),
                                      min(bx + 1, WI - 1) * (C_ / 4),
                                      min(bx + 2, WI - 1) * (C_ / 4), 0);

        z = ((wy[0] + wy[1] + wy[2]) == 0.0f) ||
            ((wx[0] + wx[1] + wx[2]) == 0.0f);
    }
    __syncwarp();

    // ---- whole warp out of bounds: direct zero stores (STG.128) ----
    if (__all_sync(FULL, z)) {
        float4 zv = make_float4(0.f, 0.f, 0.f, 0.f);
        #pragma unroll
        for (int k = 0; k < 8; k++) {
            int c = (k << 2) | (lane >> 3);
            int piece = lane & 7;
            *(float4*)(outp + (long long)c * (HU * WU) + (piece << 2)) = zv;
        }
        return;
    }

    // ---- 8 passes of 4 points x 32 channels ----
    int g  = lane >> 3;                  // point within pass
    int lc = lane & 7;                   // channel quad
    const float4* xp = g_nhwc4 + (long long)n * (HI * WI * (C_ / 4)) + lc;

    for (int pass = 0; pass < 8; pass++) {
        int src = (pass << 2) | g;
        const float* tp = tap[w][src];
        // 5 broadcast LDS
        float4 Wa = *(const float4*)(tp + 0);
        float4 Wb = *(const float4*)(tp + 4);
        float  w8 = tp[8];
        int4   RO = *(const int4*)(tp + 12);
        int4   CO = *(const int4*)(tp + 16);

        float wij[9] = {Wa.x, Wa.y, Wa.z, Wa.w, Wb.x, Wb.y, Wb.z, Wb.w, w8};

        unsigned long long acc01 = 0ull, acc23 = 0ull;
        unsigned long long t[10];

        // Wave 1: taps 0..4 (5 loads in flight), then predicated FMAs
        pred_load2(t[0], t[1], xp + RO.x + CO.x, wij[0]);
        pred_load2(t[2], t[3], xp + RO.x + CO.y, wij[1]);
        pred_load2(t[4], t[5], xp + RO.x + CO.z, wij[2]);
        pred_load2(t[6], t[7], xp + RO.y + CO.x, wij[3]);
        pred_load2(t[8], t[9], xp + RO.y + CO.y, wij[4]);
        #pragma unroll
        for (int k = 0; k < 5; k++) {
            unsigned long long w2;
            PACK2(w2, wij[k]);
            pred_fma2(acc01, acc23, t[2 * k], t[2 * k + 1], w2, wij[k]);
        }

        // Wave 2: taps 5..8 reuse t[0..7], then predicated FMAs
        pred_load2(t[0], t[1], xp + RO.y + CO.z, wij[5]);
        pred_load2(t[2], t[3], xp + RO.z + CO.x, wij[6]);
        pred_load2(t[4], t[5], xp + RO.z + CO.y, wij[7]);
        pred_load2(t[6], t[7], xp + RO.z + CO.z, wij[8]);
        #pragma unroll
        for (int k = 0; k < 4; k++) {
            unsigned long long w2;
            PACK2(w2, wij[5 + k]);
            pred_fma2(acc01, acc23, t[2 * k], t[2 * k + 1], w2, wij[5 + k]);
        }

        float ax, ay, az, aw;
        UNPACK2(ax, ay, acc01);
        UNPACK2(az, aw, acc23);

        int p  = (pass << 2) | g;
        int cb = lc << 2;
        obuf[w][cb + 0][p] = ax;         // bank = (4lc+g)+const: conflict-free
        obuf[w][cb + 1][p] = ay;
        obuf[w][cb + 2][p] = az;
        obuf[w][cb + 3][p] = aw;
    }
    __syncwarp();

    // ---- NCHW stores: 8 x STG.128 (4 channel-rows / instruction) ----
    #pragma unroll
    for (int k = 0; k < 8; k++) {
        int c = (k << 2) | (lane >> 3);
        int piece = lane & 7;
        float4 v;
        v.x = obuf[w][c][(piece << 2) + 0];   // banks distinct across lanes
        v.y = obuf[w][c][(piece << 2) + 1];
        v.z = obuf[w][c][(piece << 2) + 2];
        v.w = obuf[w][c][(piece << 2) + 3];
        *(float4*)(outp + (long long)c * (HU * WU) + (piece << 2)) = v;
    }
}

extern "C" void kernel_launch(void* const* d_in, const int* in_sizes, int n_in,
                              void* d_out, int out_size) {
    const float* x     = (const float*)d_in[0];
    const float* theta = (const float*)d_in[1];
    float*       out   = (float*)d_out;

    // one (n,h) input row per block
    transpose_nhwc<<<N_ * HI, 256>>>(x);

    // 65536 warps: one warp per 32-point output row segment (all 32 channels)
    fused_gather_nhwc<<<8192, 256>>>(theta, out);
}

// round 16
// speedup vs baseline: 3.1931x; 3.1931x over previous
#include <cuda_runtime.h>
#include <cuda_fp16.h>

// Fused upsample2x-bilinear -> affine_grid -> grid_sample_bilinear.
// Separable composition: output = 3x3 weighted sum over ORIGINAL image.
// R16: R14 skeleton (zero-init predicated loads, two waves, tap tables)
// with fp16 NHWC scratch + HFMA2 accumulation: one point's 32 channels =
// 64B, so each tap load serves 8 points/pass (4 passes instead of 8).

#define N_   8
#define C_   32
#define HI   256
#define WI   256
#define HU   512
#define WU   512

// NHWC fp16 scratch: 8*256*256 points * 64B = 33.5 MB (device global)
__device__ uint4 g_nhwcH[N_ * HI * WI * 4];

// ---------------- prepass: NCHW f32 -> NHWC fp16 tiled transpose ----------------
__global__ void __launch_bounds__(256)
transpose_nhwc_h(const float* __restrict__ x) {
    __shared__ float sm[C_][33];
    int lane = threadIdx.x & 31;
    int wp   = threadIdx.x >> 5;          // 8 warps
    int bh = blockIdx.x;                   // n*HI + h
    int w0 = blockIdx.y << 5;              // w tile origin (8 tiles)
    int n = bh >> 8, h = bh & 255;

    const float* ip = x + (((long long)n * C_) * HI + h) * WI + w0;
    #pragma unroll
    for (int k = 0; k < 4; k++) {
        int c = (k << 3) + wp;
        sm[c][lane] = ip[(long long)c * (HI * WI) + lane];  // coalesced read
    }
    __syncthreads();

    // Each thread packs 4 channels of one point into uint2 (8B), coalesced.
    int t = threadIdx.x;
    int p = t >> 3;                        // point within 32-w tile
    int o = t & 7;                         // channel oct (4 channels)
    __half2 a = __floats2half2_rn(sm[4*o + 0][p], sm[4*o + 1][p]);
    __half2 b = __floats2half2_rn(sm[4*o + 2][p], sm[4*o + 3][p]);
    uint2 v;
    v.x = *(unsigned*)&a;
    v.y = *(unsigned*)&b;
    long long P = ((long long)n * HI + h) * WI + (w0 + p);
    unsigned* op = (unsigned*)g_nhwcH + P * 16 + o * 2;
    *(uint2*)op = v;
}

// ---------------- main fused kernel ----------------
__device__ __forceinline__ void axis_taps(float f, int U, int O,
                                          int& base, float w[3]) {
    float f0 = floorf(f);
    int   i0 = (int)f0;
    float wf = f - f0;

    w[0] = 0.f; w[1] = 0.f; w[2] = 0.f;
    base = 0;

    #pragma unroll
    for (int k = 0; k < 2; k++) {
        int   t  = i0 + k;
        float Wk = (k == 0) ? (1.0f - wf) : wf;
        Wk = (t >= 0 && t < U) ? Wk : 0.0f;          // zero-padding validity
        int tc = min(max(t, 0), U - 1);
        float s  = fmaxf((float)tc * 0.5f - 0.25f, 0.0f);  // upsample source
        int   o0 = (int)s;
        float wu = s - (float)o0;
        int   o1 = min(o0 + 1, O - 1);
        if (k == 0) base = o0;                       // taps are monotone
        w[o0 - base] += Wk * (1.0f - wu);
        w[o1 - base] += Wk * wu;
    }
}

// Predicated 16B load into FRESH zero-init u32 quad (R14-safe pattern:
// outputs unconditionally written). No memory request when w2 == 0;
// HFMA2 with t==0 contributes exactly 0.
__device__ __forceinline__ void pred_load4(unsigned& a, unsigned& b,
                                           unsigned& c, unsigned& d,
                                           const uint4* addr, unsigned w2) {
    asm("{\n\t"
        ".reg .pred p;\n\t"
        "setp.ne.u32 p, %4, 0;\n\t"
        "mov.b32 %0, 0;\n\t"
        "mov.b32 %1, 0;\n\t"
        "mov.b32 %2, 0;\n\t"
        "mov.b32 %3, 0;\n\t"
        "@p ld.global.nc.v4.b32 {%0, %1, %2, %3}, [%5];\n\t"
        "}"
        : "=r"(a), "=r"(b), "=r"(c), "=r"(d)
        : "r"(w2), "l"((const void*)addr));
}

#define HFMA2(acc, a, b) \
    asm("fma.rn.f16x2 %0, %1, %2, %0;" : "+r"(acc) : "r"(a), "r"(b))
#define HADD2(d, a, b) \
    asm("add.rn.f16x2 %0, %1, %2;" : "=r"(d) : "r"(a), "r"(b))

__global__ void __launch_bounds__(256, 4)
fused_gather_nhwc(const float* __restrict__ theta,
                  float* __restrict__ out) {
    __shared__ float obuf[8][C_][33];           // [warp][channel][point]
    // per-point tap table (20 u32): [0..8]=half2{w,w} wij, [12..15]=RO,
    // [16..19]=CO (uint4-unit offsets). Stride 80B: 16B-aligned fields.
    __shared__ __align__(16) unsigned tap[8][32][20];

    const unsigned FULL = 0xFFFFFFFFu;
    int w    = threadIdx.x >> 5;
    int lane = threadIdx.x & 31;
    int wid  = blockIdx.x * 8 + w;
    int n   = wid >> 13;                 // 8192 warps per image
    int r   = wid & 8191;
    int yo  = r >> 4;                    // 512 rows
    int xo0 = (r & 15) << 5;             // 16 x-segments of 32

    float* outp = out + ((long long)n * C_) * (HU * WU)
                      + (long long)yo * WU + xo0;

    const float* th = theta + n * 6;
    float t0 = __ldg(th + 0), t1 = __ldg(th + 1), t2 = __ldg(th + 2);
    float t3 = __ldg(th + 3), t4 = __ldg(th + 4), t5 = __ldg(th + 5);
    float gyn = (2.0f * (float)yo + 1.0f) / (float)HU - 1.0f;

    // ---- per-lane taps for point (xo0+lane, yo) -> SMEM table ----
    int z;
    {
        int xo = xo0 + lane;
        float gxn = (2.0f * (float)xo + 1.0f) / (float)WU - 1.0f;
        float gox = t0 * gxn + t1 * gyn + t2;
        float goy = t3 * gxn + t4 * gyn + t5;
        float ix = ((gox + 1.0f) * (float)WU - 1.0f) * 0.5f;
        float iy = ((goy + 1.0f) * (float)HU - 1.0f) * 0.5f;

        int by, bx;
        float wy[3], wx[3];
        axis_taps(iy, HU, HI, by, wy);
        axis_taps(ix, WU, WI, bx, wx);

        unsigned* tp = tap[w][lane];
        #pragma unroll
        for (int i = 0; i < 3; i++)
            #pragma unroll
            for (int j = 0; j < 3; j++) {
                __half2 h2 = __float2half2_rn(wy[i] * wx[j]);
                tp[i * 3 + j] = *(unsigned*)&h2;
            }
        *(int4*)(tp + 12) = make_int4(min(by,     HI - 1) * (WI * 4),
                                      min(by + 1, HI - 1) * (WI * 4),
                                      min(by + 2, HI - 1) * (WI * 4), 0);
        *(int4*)(tp + 16) = make_int4(min(bx,     WI - 1) * 4,
                                      min(bx + 1, WI - 1) * 4,
                                      min(bx + 2, WI - 1) * 4, 0);

        z = ((wy[0] + wy[1] + wy[2]) == 0.0f) ||
            ((wx[0] + wx[1] + wx[2]) == 0.0f);
    }
    __syncwarp();

    // ---- whole warp out of bounds: direct zero stores (STG.128) ----
    if (__all_sync(FULL, z)) {
        float4 zv = make_float4(0.f, 0.f, 0.f, 0.f);
        #pragma unroll
        for (int k = 0; k < 8; k++) {
            int c = (k << 2) | (lane >> 3);
            int piece = lane & 7;
            *(float4*)(outp + (long long)c * (HU * WU) + (piece << 2)) = zv;
        }
        return;
    }

    // ---- 4 passes of 8 points x 32 channels ----
    int g   = lane >> 2;                 // point within pass (0..7)
    int lc2 = lane & 3;                  // channel oct quad (8 channels)
    const uint4* xp = g_nhwcH + (long long)n * (HI * WI * 4) + lc2;

    for (int pass = 0; pass < 4; pass++) {
        int src = (pass << 3) | g;
        const unsigned* tp = tap[w][src];
        // broadcast LDS: stride 20 words -> 8 srcs hit distinct bank quads
        uint4 Wa = *(const uint4*)(tp + 0);
        uint4 Wb = *(const uint4*)(tp + 4);
        unsigned w8 = tp[8];
        int4  RO = *(const int4*)(tp + 12);
        int4  CO = *(const int4*)(tp + 16);

        unsigned W[9] = {Wa.x, Wa.y, Wa.z, Wa.w, Wb.x, Wb.y, Wb.z, Wb.w, w8};

        unsigned accA0 = 0, accA1 = 0, accA2 = 0, accA3 = 0;
        unsigned accB0 = 0, accB1 = 0, accB2 = 0, accB3 = 0;
        unsigned t[20];

        // Wave 1: taps 0..4 (5 loads in flight), then HFMA2s
        pred_load4(t[0],  t[1],  t[2],  t[3],  xp + RO.x + CO.x, W[0]);
        pred_load4(t[4],  t[5],  t[6],  t[7],  xp + RO.x + CO.y, W[1]);
        pred_load4(t[8],  t[9],  t[10], t[11], xp + RO.x + CO.z, W[2]);
        pred_load4(t[12], t[13], t[14], t[15], xp + RO.y + CO.x, W[3]);
        pred_load4(t[16], t[17], t[18], t[19], xp + RO.y + CO.y, W[4]);
        #pragma unroll
        for (int k = 0; k < 5; k++) {
            if (k & 1) {
                HFMA2(accB0, t[4*k+0], W[k]); HFMA2(accB1, t[4*k+1], W[k]);
                HFMA2(accB2, t[4*k+2], W[k]); HFMA2(accB3, t[4*k+3], W[k]);
            } else {
                HFMA2(accA0, t[4*k+0], W[k]); HFMA2(accA1, t[4*k+1], W[k]);
                HFMA2(accA2, t[4*k+2], W[k]); HFMA2(accA3, t[4*k+3], W[k]);
            }
        }

        // Wave 2: taps 5..8 reuse t[0..15], then HFMA2s
        pred_load4(t[0],  t[1],  t[2],  t[3],  xp + RO.y + CO.z, W[5]);
        pred_load4(t[4],  t[5],  t[6],  t[7],  xp + RO.z + CO.x, W[6]);
        pred_load4(t[8],  t[9],  t[10], t[11], xp + RO.z + CO.y, W[7]);
        pred_load4(t[12], t[13], t[14], t[15], xp + RO.z + CO.z, W[8]);
        #pragma unroll
        for (int k = 0; k < 4; k++) {
            if (k & 1) {
                HFMA2(accA0, t[4*k+0], W[5+k]); HFMA2(accA1, t[4*k+1], W[5+k]);
                HFMA2(accA2, t[4*k+2], W[5+k]); HFMA2(accA3, t[4*k+3], W[5+k]);
            } else {
                HFMA2(accB0, t[4*k+0], W[5+k]); HFMA2(accB1, t[4*k+1], W[5+k]);
                HFMA2(accB2, t[4*k+2], W[5+k]); HFMA2(accB3, t[4*k+3], W[5+k]);
            }
        }

        unsigned s0, s1, s2, s3;
        HADD2(s0, accA0, accB0); HADD2(s1, accA1, accB1);
        HADD2(s2, accA2, accB2); HADD2(s3, accA3, accB3);

        // convert 4 half2 -> 8 f32, stage to obuf (banks distinct: 8lc2+g)
        int p  = (pass << 3) | g;
        int cb = lc2 << 3;
        float2 f0 = __half22float2(*(__half2*)&s0);
        float2 f1 = __half22float2(*(__half2*)&s1);
        float2 f2 = __half22float2(*(__half2*)&s2);
        float2 f3 = __half22float2(*(__half2*)&s3);
        obuf[w][cb + 0][p] = f0.x;  obuf[w][cb + 1][p] = f0.y;
        obuf[w][cb + 2][p] = f1.x;  obuf[w][cb + 3][p] = f1.y;
        obuf[w][cb + 4][p] = f2.x;  obuf[w][cb + 5][p] = f2.y;
        obuf[w][cb + 6][p] = f3.x;  obuf[w][cb + 7][p] = f3.y;
    }
    __syncwarp();

    // ---- NCHW stores: 8 x STG.128 (4 channel-rows / instruction) ----
    #pragma unroll
    for (int k = 0; k < 8; k++) {
        int c = (k << 2) | (lane >> 3);
        int piece = lane & 7;
        float4 v;
        v.x = obuf[w][c][(piece << 2) + 0];   // banks distinct across lanes
        v.y = obuf[w][c][(piece << 2) + 1];
        v.z = obuf[w][c][(piece << 2) + 2];
        v.w = obuf[w][c][(piece << 2) + 3];
        *(float4*)(outp + (long long)c * (HU * WU) + (piece << 2)) = v;
    }
}

extern "C" void kernel_launch(void* const* d_in, const int* in_sizes, int n_in,
                              void* d_out, int out_size) {
    const float* x     = (const float*)d_in[0];
    const float* theta = (const float*)d_in[1];
    float*       out   = (float*)d_out;

    dim3 tg(N_ * HI, WI / 32);           // (2048, 8) tiles of 32c x 32w
    transpose_nhwc_h<<<tg, 256>>>(x);

    // 65536 warps: one warp per 32-point output row segment (all 32 channels)
    fused_gather_nhwc<<<8192, 256>>>(theta, out);
}

// round 17
// speedup vs baseline: 3.3509x; 1.0494x over previous
#include <cuda_runtime.h>
#include <cuda_fp16.h>

// Fused upsample2x-bilinear -> affine_grid -> grid_sample_bilinear.
// Separable composition: output = 3x3 weighted sum over ORIGINAL image.
// R17: R16 + selective predication (taps 0,1,3,4 are ~never zero -> plain
// loads; index-2 taps are zero ~50% -> keep predicated skip) + leaner
// prepass (LDG.128, 2 rows/block).

#define N_   8
#define C_   32
#define HI   256
#define WI   256
#define HU   512
#define WU   512

// NHWC fp16 scratch: 8*256*256 points * 64B = 33.5 MB (device global)
__device__ uint4 g_nhwcH[N_ * HI * WI * 4];

// ---------------- prepass: NCHW f32 -> NHWC fp16, 2 rows per block ----------------
__global__ void __launch_bounds__(256)
transpose_nhwc_h(const float* __restrict__ x) {
    __shared__ float sm[2][C_][33];
    int t  = threadIdx.x;
    int bh = blockIdx.x;                   // n*128 + h/2
    int w0 = blockIdx.y << 5;              // w tile origin (8 tiles)
    int n = bh >> 7, h2 = (bh & 127) << 1;

    // Load: thread (ch, idx) pulls float4 of channel ch, cols w0+4idx..+3
    int ch  = t >> 3;                      // 0..31
    int idx = t & 7;                       // 0..7
    const float* ip = x + ((long long)n * C_ + ch) * (HI * WI)
                        + (long long)h2 * WI + w0 + (idx << 2);
    #pragma unroll
    for (int hh = 0; hh < 2; hh++) {
        float4 v = *(const float4*)(ip + hh * WI);
        sm[hh][ch][(idx << 2) + 0] = v.x;  // bank (ch+4idx+j)%32: distinct
        sm[hh][ch][(idx << 2) + 1] = v.y;
        sm[hh][ch][(idx << 2) + 2] = v.z;
        sm[hh][ch][(idx << 2) + 3] = v.w;
    }
    __syncthreads();

    // Store: thread (p, o) packs 4 channels of point p into uint2, coalesced
    int p = t >> 3;                        // point within 32-w tile
    int o = t & 7;                         // channel oct (4 channels)
    #pragma unroll
    for (int hh = 0; hh < 2; hh++) {
        __half2 a = __floats2half2_rn(sm[hh][4*o + 0][p], sm[hh][4*o + 1][p]);
        __half2 b = __floats2half2_rn(sm[hh][4*o + 2][p], sm[hh][4*o + 3][p]);
        uint2 v;
        v.x = *(unsigned*)&a;
        v.y = *(unsigned*)&b;
        long long P = ((long long)n * HI + h2 + hh) * WI + (w0 + p);
        *(uint2*)((unsigned*)g_nhwcH + P * 16 + o * 2) = v;
    }
}

// ---------------- main fused kernel ----------------
__device__ __forceinline__ void axis_taps(float f, int U, int O,
                                          int& base, float w[3]) {
    float f0 = floorf(f);
    int   i0 = (int)f0;
    float wf = f - f0;

    w[0] = 0.f; w[1] = 0.f; w[2] = 0.f;
    base = 0;

    #pragma unroll
    for (int k = 0; k < 2; k++) {
        int   t  = i0 + k;
        float Wk = (k == 0) ? (1.0f - wf) : wf;
        Wk = (t >= 0 && t < U) ? Wk : 0.0f;          // zero-padding validity
        int tc = min(max(t, 0), U - 1);
        float s  = fmaxf((float)tc * 0.5f - 0.25f, 0.0f);  // upsample source
        int   o0 = (int)s;
        float wu = s - (float)o0;
        int   o1 = min(o0 + 1, O - 1);
        if (k == 0) base = o0;                       // taps are monotone
        w[o0 - base] += Wk * (1.0f - wu);
        w[o1 - base] += Wk * wu;
    }
}

// Predicated 16B load into FRESH zero-init u32 quad (outputs always
// written -> register-allocator safe). No memory request when w2 == 0.
__device__ __forceinline__ void pred_load4(unsigned& a, unsigned& b,
                                           unsigned& c, unsigned& d,
                                           const uint4* addr, unsigned w2) {
    asm("{\n\t"
        ".reg .pred p;\n\t"
        "setp.ne.u32 p, %4, 0;\n\t"
        "mov.b32 %0, 0;\n\t"
        "mov.b32 %1, 0;\n\t"
        "mov.b32 %2, 0;\n\t"
        "mov.b32 %3, 0;\n\t"
        "@p ld.global.nc.v4.b32 {%0, %1, %2, %3}, [%5];\n\t"
        "}"
        : "=r"(a), "=r"(b), "=r"(c), "=r"(d)
        : "r"(w2), "l"((const void*)addr));
}

#define HFMA2(acc, a, b) \
    asm("fma.rn.f16x2 %0, %1, %2, %0;" : "+r"(acc) : "r"(a), "r"(b))
#define HADD2(d, a, b) \
    asm("add.rn.f16x2 %0, %1, %2;" : "=r"(d) : "r"(a), "r"(b))

__global__ void __launch_bounds__(256, 4)
fused_gather_nhwc(const float* __restrict__ theta,
                  float* __restrict__ out) {
    __shared__ float obuf[8][C_][33];           // [warp][channel][point]
    // per-point tap table (20 u32): [0..8]=half2{w,w} wij, [12..15]=RO,
    // [16..19]=CO (uint4-unit offsets).
    __shared__ __align__(16) unsigned tap[8][32][20];

    const unsigned FULL = 0xFFFFFFFFu;
    int w    = threadIdx.x >> 5;
    int lane = threadIdx.x & 31;
    int wid  = blockIdx.x * 8 + w;
    int n   = wid >> 13;                 // 8192 warps per image
    int r   = wid & 8191;
    int yo  = r >> 4;                    // 512 rows
    int xo0 = (r & 15) << 5;             // 16 x-segments of 32

    float* outp = out + ((long long)n * C_) * (HU * WU)
                      + (long long)yo * WU + xo0;

    const float* th = theta + n * 6;
    float t0 = __ldg(th + 0), t1 = __ldg(th + 1), t2 = __ldg(th + 2);
    float t3 = __ldg(th + 3), t4 = __ldg(th + 4), t5 = __ldg(th + 5);
    float gyn = (2.0f * (float)yo + 1.0f) / (float)HU - 1.0f;

    // ---- per-lane taps for point (xo0+lane, yo) -> SMEM table ----
    int z;
    {
        int xo = xo0 + lane;
        float gxn = (2.0f * (float)xo + 1.0f) / (float)WU - 1.0f;
        float gox = t0 * gxn + t1 * gyn + t2;
        float goy = t3 * gxn + t4 * gyn + t5;
        float ix = ((gox + 1.0f) * (float)WU - 1.0f) * 0.5f;
        float iy = ((goy + 1.0f) * (float)HU - 1.0f) * 0.5f;

        int by, bx;
        float wy[3], wx[3];
        axis_taps(iy, HU, HI, by, wy);
        axis_taps(ix, WU, WI, bx, wx);

        unsigned* tp = tap[w][lane];
        #pragma unroll
        for (int i = 0; i < 3; i++)
            #pragma unroll
            for (int j = 0; j < 3; j++) {
                __half2 h2 = __float2half2_rn(wy[i] * wx[j]);
                tp[i * 3 + j] = *(unsigned*)&h2;
            }
        *(int4*)(tp + 12) = make_int4(min(by,     HI - 1) * (WI * 4),
                                      min(by + 1, HI - 1) * (WI * 4),
                                      min(by + 2, HI - 1) * (WI * 4), 0);
        *(int4*)(tp + 16) = make_int4(min(bx,     WI - 1) * 4,
                                      min(bx + 1, WI - 1) * 4,
                                      min(bx + 2, WI - 1) * 4, 0);

        z = ((wy[0] + wy[1] + wy[2]) == 0.0f) ||
            ((wx[0] + wx[1] + wx[2]) == 0.0f);
    }
    __syncwarp();

    // ---- whole warp out of bounds: direct zero stores (STG.128) ----
    if (__all_sync(FULL, z)) {
        float4 zv = make_float4(0.f, 0.f, 0.f, 0.f);
        #pragma unroll
        for (int k = 0; k < 8; k++) {
            int c = (k << 2) | (lane >> 3);
            int piece = lane & 7;
            *(float4*)(outp + (long long)c * (HU * WU) + (piece << 2)) = zv;
        }
        return;
    }

    // ---- 4 passes of 8 points x 32 channels ----
    int g   = lane >> 2;                 // point within pass (0..7)
    int lc2 = lane & 3;                  // channel oct quad (8 channels)
    const uint4* xp = g_nhwcH + (long long)n * (HI * WI * 4) + lc2;

    for (int pass = 0; pass < 4; pass++) {
        int src = (pass << 3) | g;
        const unsigned* tp = tap[w][src];
        uint4 Wa = *(const uint4*)(tp + 0);
        uint4 Wb = *(const uint4*)(tp + 4);
        unsigned w8 = tp[8];
        int4  RO = *(const int4*)(tp + 12);
        int4  CO = *(const int4*)(tp + 16);

        unsigned W[9] = {Wa.x, Wa.y, Wa.z, Wa.w, Wb.x, Wb.y, Wb.z, Wb.w, w8};

        unsigned accA0 = 0, accA1 = 0, accA2 = 0, accA3 = 0;
        unsigned accB0 = 0, accB1 = 0, accB2 = 0, accB3 = 0;
        unsigned t[20];

        // Wave 1: taps 0..4. Taps 0,1,3,4 (~never zero) load plain;
        // tap 2 (zero ~50%) predicated.
        {
            uint4 a0 = __ldg(xp + RO.x + CO.x);
            uint4 a1 = __ldg(xp + RO.x + CO.y);
            pred_load4(t[8], t[9], t[10], t[11], xp + RO.x + CO.z, W[2]);
            uint4 a3 = __ldg(xp + RO.y + CO.x);
            uint4 a4 = __ldg(xp + RO.y + CO.y);
            t[0]=a0.x; t[1]=a0.y; t[2]=a0.z; t[3]=a0.w;
            t[4]=a1.x; t[5]=a1.y; t[6]=a1.z; t[7]=a1.w;
            t[12]=a3.x; t[13]=a3.y; t[14]=a3.z; t[15]=a3.w;
            t[16]=a4.x; t[17]=a4.y; t[18]=a4.z; t[19]=a4.w;
        }
        #pragma unroll
        for (int k = 0; k < 5; k++) {
            if (k & 1) {
                HFMA2(accB0, t[4*k+0], W[k]); HFMA2(accB1, t[4*k+1], W[k]);
                HFMA2(accB2, t[4*k+2], W[k]); HFMA2(accB3, t[4*k+3], W[k]);
            } else {
                HFMA2(accA0, t[4*k+0], W[k]); HFMA2(accA1, t[4*k+1], W[k]);
                HFMA2(accA2, t[4*k+2], W[k]); HFMA2(accA3, t[4*k+3], W[k]);
            }
        }

        // Wave 2: taps 5..8 (all contain an index-2 row/col: zero ~50-75%)
        pred_load4(t[0],  t[1],  t[2],  t[3],  xp + RO.y + CO.z, W[5]);
        pred_load4(t[4],  t[5],  t[6],  t[7],  xp + RO.z + CO.x, W[6]);
        pred_load4(t[8],  t[9],  t[10], t[11], xp + RO.z + CO.y, W[7]);
        pred_load4(t[12], t[13], t[14], t[15], xp + RO.z + CO.z, W[8]);
        #pragma unroll
        for (int k = 0; k < 4; k++) {
            if (k & 1) {
                HFMA2(accA0, t[4*k+0], W[5+k]); HFMA2(accA1, t[4*k+1], W[5+k]);
                HFMA2(accA2, t[4*k+2], W[5+k]); HFMA2(accA3, t[4*k+3], W[5+k]);
            } else {
                HFMA2(accB0, t[4*k+0], W[5+k]); HFMA2(accB1, t[4*k+1], W[5+k]);
                HFMA2(accB2, t[4*k+2], W[5+k]); HFMA2(accB3, t[4*k+3], W[5+k]);
            }
        }

        unsigned s0, s1, s2, s3;
        HADD2(s0, accA0, accB0); HADD2(s1, accA1, accB1);
        HADD2(s2, accA2, accB2); HADD2(s3, accA3, accB3);

        // convert 4 half2 -> 8 f32, stage to obuf (banks distinct: 8lc2+g)
        int p  = (pass << 3) | g;
        int cb = lc2 << 3;
        float2 f0 = __half22float2(*(__half2*)&s0);
        float2 f1 = __half22float2(*(__half2*)&s1);
        float2 f2 = __half22float2(*(__half2*)&s2);
        float2 f3 = __half22float2(*(__half2*)&s3);
        obuf[w][cb + 0][p] = f0.x;  obuf[w][cb + 1][p] = f0.y;
        obuf[w][cb + 2][p] = f1.x;  obuf[w][cb + 3][p] = f1.y;
        obuf[w][cb + 4][p] = f2.x;  obuf[w][cb + 5][p] = f2.y;
        obuf[w][cb + 6][p] = f3.x;  obuf[w][cb + 7][p] = f3.y;
    }
    __syncwarp();

    // ---- NCHW stores: 8 x STG.128 (4 channel-rows / instruction) ----
    #pragma unroll
    for (int k = 0; k < 8; k++) {
        int c = (k << 2) | (lane >> 3);
        int piece = lane & 7;
        float4 v;
        v.x = obuf[w][c][(piece << 2) + 0];   // banks distinct across lanes
        v.y = obuf[w][c][(piece << 2) + 1];
        v.z = obuf[w][c][(piece << 2) + 2];
        v.w = obuf[w][c][(piece << 2) + 3];
        *(float4*)(outp + (long long)c * (HU * WU) + (piece << 2)) = v;
    }
}

extern "C" void kernel_launch(void* const* d_in, const int* in_sizes, int n_in,
                              void* d_out, int out_size) {
    const float* x     = (const float*)d_in[0];
    const float* theta = (const float*)d_in[1];
    float*       out   = (float*)d_out;

    dim3 tg(N_ * HI / 2, WI / 32);       // (1024, 8): 2 rows per block
    transpose_nhwc_h<<<tg, 256>>>(x);

    // 65536 warps: one warp per 32-point output row segment (all 32 channels)
    fused_gather_nhwc<<<8192, 256>>>(theta, out);
}